// round 12
// baseline (speedup 1.0000x reference)
#include <cuda_runtime.h>
#include <cuda_bf16.h>
#include <math.h>

#define T_SEQ   2048
#define BATCH   2
#define DM      1024
#define NH      16
#define DH      64
#define MROWS   (BATCH*T_SEQ)    /* 4096 */
#define N_QKV   (3*DM)           /* 3072 */

// Scratch (allocation-free rule: __device__ globals).
__device__ float g_Q[MROWS*DM];
__device__ float g_K[MROWS*DM];
__device__ float g_V[MROWS*DM];
__device__ float g_attn[MROWS*DM];
__device__ float g_WqT[N_QKV*DM];   // W_qkv transposed [n][k]
__device__ float g_WpT[DM*DM];      // W_proj transposed [n][k]

// ---------------------------------------------------------------------------
// bf16 split helpers: x = hi + lo with |x - hi - lo| ~ 2^-18 |x|.
// pack two (even, odd) bf16 into one 32-bit fragment word (low = even).
// ---------------------------------------------------------------------------
__device__ __forceinline__ void split2(float a, float b, unsigned &hi, unsigned &lo)
{
    __nv_bfloat16 ha = __float2bfloat16_rn(a);
    __nv_bfloat16 hb = __float2bfloat16_rn(b);
    __nv_bfloat162 h; h.x = ha; h.y = hb;
    hi = *reinterpret_cast<unsigned*>(&h);
    __nv_bfloat162 l = __floats2bfloat162_rn(a - __bfloat162float(ha),
                                             b - __bfloat162float(hb));
    lo = *reinterpret_cast<unsigned*>(&l);
}

__device__ __forceinline__ void mma16816(float* d,
    unsigned a0, unsigned a1, unsigned a2, unsigned a3,
    unsigned b0, unsigned b1)
{
    asm volatile(
        "mma.sync.aligned.m16n8k16.row.col.f32.bf16.bf16.f32 "
        "{%0,%1,%2,%3}, {%4,%5,%6,%7}, {%8,%9}, {%0,%1,%2,%3};\n"
        : "+f"(d[0]), "+f"(d[1]), "+f"(d[2]), "+f"(d[3])
        : "r"(a0), "r"(a1), "r"(a2), "r"(a3), "r"(b0), "r"(b1));
}

// ---------------------------------------------------------------------------
// Prep: transpose W[k][N] -> WT[n][k] (fp32, no split). 64x64 tiles.
// Smem loads/stores coalesced; one-time cost ~5-10us for 16MB.
// ---------------------------------------------------------------------------
__global__ __launch_bounds__(256)
void wtrans_kernel(const float* __restrict__ W, float* __restrict__ WT, int N)
{
    __shared__ float sw[64][68];
    const int tid = threadIdx.x;
    const int k0 = blockIdx.x * 64;
    const int n0 = blockIdx.y * 64;

#pragma unroll
    for (int i = 0; i < 4; i++) {
        const int row = (tid >> 4) + i * 16;   // k within tile
        const int col = (tid & 15) * 4;        // n within tile
        *(float4*)&sw[row][col] =
            *(const float4*)&W[(size_t)(k0 + row) * N + n0 + col];
    }
    __syncthreads();

    // write WT rows: lane group covers consecutive k for coalesced stores
    const int kq = (tid & 15) * 4;     // k base 0..60
    const int nb = tid >> 4;           // 0..15
#pragma unroll
    for (int i = 0; i < 4; i++) {
        const int n = nb + i * 16;
        float4 v;
        v.x = sw[kq + 0][n];
        v.y = sw[kq + 1][n];
        v.z = sw[kq + 2][n];
        v.w = sw[kq + 3][n];
        *(float4*)&WT[(size_t)(n0 + n) * DM + k0 + kq] = v;
    }
}

// ---------------------------------------------------------------------------
// Tensor-core GEMM (R6 structure EXACTLY: single buffer, two syncs per iter,
// fp32 LDG before barrier + split2 after). Only change vs R6: B reads the
// pre-transposed WT[n][k], so B staging is identical to A staging
// (4x LDG.128/thread/iter instead of 16 scalar gathers).
// Block 128x128x32, 8 warps (2x4), warp tile 64x32. 3-MMA bf16 split.
// ---------------------------------------------------------------------------
template<bool SCATTER>
__global__ __launch_bounds__(256, 2)
void mma_gemm_kernel(const float* __restrict__ Ain, const float* __restrict__ WT,
                     const float* __restrict__ bias, float* __restrict__ out)
{
    __shared__ unsigned Ahi[128*20], Alo[128*20], Bhi[128*20], Blo[128*20];

    const float* __restrict__ A = SCATTER ? Ain : (const float*)g_attn;

    const int tid  = threadIdx.x;
    const int lane = tid & 31;
    const int warp = tid >> 5;
    const int wm   = warp >> 2;     // 0..1
    const int wn   = warp & 3;      // 0..3
    const int g    = lane >> 2;     // 0..7
    const int t    = lane & 3;      // 0..3
    const int m0   = blockIdx.y * 128;
    const int n0   = blockIdx.x * 128;

    float acc[4][4][4];
#pragma unroll
    for (int mt = 0; mt < 4; mt++)
#pragma unroll
        for (int nt = 0; nt < 4; nt++)
#pragma unroll
            for (int i = 0; i < 4; i++) acc[mt][nt][i] = 0.f;

    const int ar = tid >> 3;          // row 0..31 (step 32)
    const int ak = (tid & 7) << 2;    // k offset 0,4,..,28

    for (int k0 = 0; k0 < DM; k0 += 32) {
        // ---- issue ALL loads before the barrier (R6's winning property:
        //      barrier warp-skew absorbs LDG latency) ----
        float4 av[4], bv[4];
#pragma unroll
        for (int ii = 0; ii < 4; ii++) {
            const int r = ar + ii * 32;
            av[ii] = *(const float4*)&A [(size_t)(m0 + r) * DM + k0 + ak];
            bv[ii] = *(const float4*)&WT[(size_t)(n0 + r) * DM + k0 + ak];
        }
        __syncthreads();               // previous tile fully consumed
#pragma unroll
        for (int ii = 0; ii < 4; ii++) {
            const int r = ar + ii * 32;
            const int w = r * 20 + (ak >> 1);
            unsigned h0, l0, h1, l1;
            split2(av[ii].x, av[ii].y, h0, l0);
            split2(av[ii].z, av[ii].w, h1, l1);
            Ahi[w] = h0; Ahi[w + 1] = h1;
            Alo[w] = l0; Alo[w + 1] = l1;
            split2(bv[ii].x, bv[ii].y, h0, l0);
            split2(bv[ii].z, bv[ii].w, h1, l1);
            Bhi[w] = h0; Bhi[w + 1] = h1;
            Blo[w] = l0; Blo[w + 1] = l1;
        }
        __syncthreads();

        // ---- compute: 2 k16-steps, 4x4 fragments, 3 MMAs each ----
#pragma unroll
        for (int ks = 0; ks < 2; ks++) {
            unsigned ah[4][4], al[4][4], bh[4][2], bl[4][2];
#pragma unroll
            for (int mt = 0; mt < 4; mt++) {
                const int base = (wm * 64 + mt * 16 + g) * 20 + ks * 8 + t;
                ah[mt][0] = Ahi[base];       ah[mt][1] = Ahi[base + 160];
                ah[mt][2] = Ahi[base + 4];   ah[mt][3] = Ahi[base + 164];
                al[mt][0] = Alo[base];       al[mt][1] = Alo[base + 160];
                al[mt][2] = Alo[base + 4];   al[mt][3] = Alo[base + 164];
            }
#pragma unroll
            for (int nt = 0; nt < 4; nt++) {
                const int base = (wn * 32 + nt * 8 + g) * 20 + ks * 8 + t;
                bh[nt][0] = Bhi[base];       bh[nt][1] = Bhi[base + 4];
                bl[nt][0] = Blo[base];       bl[nt][1] = Blo[base + 4];
            }
#pragma unroll
            for (int mt = 0; mt < 4; mt++)
#pragma unroll
                for (int nt = 0; nt < 4; nt++) {
                    mma16816(acc[mt][nt], ah[mt][0], ah[mt][1], ah[mt][2], ah[mt][3],
                             bh[nt][0], bh[nt][1]);
                    mma16816(acc[mt][nt], ah[mt][0], ah[mt][1], ah[mt][2], ah[mt][3],
                             bl[nt][0], bl[nt][1]);
                    mma16816(acc[mt][nt], al[mt][0], al[mt][1], al[mt][2], al[mt][3],
                             bh[nt][0], bh[nt][1]);
                }
        }
    }

    // ---- epilogue (R6): scatter Q/K/V fp32 head-major, or proj output ----
#pragma unroll
    for (int mt = 0; mt < 4; mt++) {
        const int mrow0 = m0 + wm * 64 + mt * 16 + g;
#pragma unroll
        for (int nt = 0; nt < 4; nt++) {
            const int c = n0 + wn * 32 + nt * 8 + 2 * t;
            const float b0 = bias[c], b1 = bias[c + 1];
            const float v00 = acc[mt][nt][0] + b0;
            const float v01 = acc[mt][nt][1] + b1;
            const float v10 = acc[mt][nt][2] + b0;
            const float v11 = acc[mt][nt][3] + b1;
            if (SCATTER) {
                const int which = c >> 10;
                const int cc = c & (DM - 1);
                const int h  = cc >> 6;
                const int d  = cc & (DH - 1);
                float* dst = (which == 0) ? g_Q : (which == 1) ? g_K : g_V;
#pragma unroll
                for (int rr = 0; rr < 2; rr++) {
                    const int m   = mrow0 + rr * 8;
                    const int bb  = m >> 11;
                    const int tok = m & (T_SEQ - 1);
                    const size_t idx = ((size_t)(bb * NH + h) * T_SEQ + tok) * DH + d;
                    *(float2*)&dst[idx] = rr ? make_float2(v10, v11)
                                             : make_float2(v00, v01);
                }
            } else {
                *(float2*)&out[(size_t)mrow0 * DM + c]       = make_float2(v00, v01);
                *(float2*)&out[(size_t)(mrow0 + 8) * DM + c] = make_float2(v10, v11);
            }
        }
    }
}

// ---------------------------------------------------------------------------
// Attention (R6 verbatim): causal flash attention on tensor cores.
// CTA = 64 query rows x one (b,h); 4 warps, warp owns 16 rows.
// S = (Q*0.125) K^T via bf16 hi/lo split (3 MMAs); online softmax in regs;
// P reuses S's C-fragment layout as the A-fragment of P.V (no smem for P);
// V staged transposed [d][key] so B-fragments load conflict-free.
// ---------------------------------------------------------------------------
#define ASTR 36
__global__ __launch_bounds__(128)
void attn_mma_kernel()
{
    extern __shared__ unsigned smu[];
    unsigned* sQh = smu;
    unsigned* sQl = smu + 64 * ASTR;
    unsigned* sKh = smu + 2 * 64 * ASTR;
    unsigned* sKl = smu + 3 * 64 * ASTR;
    unsigned* sVh = smu + 4 * 64 * ASTR;   // transposed: [d][keypair]
    unsigned* sVl = smu + 5 * 64 * ASTR;

    const int tid  = threadIdx.x;
    const int lane = tid & 31;
    const int w    = tid >> 5;      // warp 0..3, rows 16w..16w+15
    const int g    = lane >> 2;     // 0..7
    const int t    = lane & 3;      // 0..3
    const int qt   = (int)(gridDim.x - 1) - (int)blockIdx.x;  // longest first
    const int bh   = blockIdx.y;
    const int q0   = qt * 64;

    const float* Qg = g_Q + (size_t)bh * T_SEQ * DH;
    const float* Kg = g_K + (size_t)bh * T_SEQ * DH;
    const float* Vg = g_V + (size_t)bh * T_SEQ * DH;

    // ---- stage Q once, pre-scaled by 1/sqrt(Dh) ----
#pragma unroll
    for (int i = 0; i < 8; i++) {
        const int idx = tid + i * 128;
        const int row = idx >> 4;
        const int dq  = (idx & 15) << 2;
        float4 v = *(const float4*)&Qg[(q0 + row) * DH + dq];
        unsigned h0, l0, h1, l1;
        split2(v.x * 0.125f, v.y * 0.125f, h0, l0);
        split2(v.z * 0.125f, v.w * 0.125f, h1, l1);
        const int wo = row * ASTR + (dq >> 1);
        sQh[wo] = h0; sQh[wo + 1] = h1;
        sQl[wo] = l0; sQl[wo + 1] = l1;
    }

    float oacc[8][4];
#pragma unroll
    for (int nf = 0; nf < 8; nf++)
#pragma unroll
        for (int i = 0; i < 4; i++) oacc[nf][i] = 0.f;
    float mrun0 = -INFINITY, mrun1 = -INFINITY;
    float lrun0 = 0.f, lrun1 = 0.f;

    for (int kt = 0; kt <= qt; kt++) {
        __syncthreads();   // Q visible (iter 0) / prior frag reads done
        const int k0 = kt * 64;

        // ---- stage K natural [key][d] ----
#pragma unroll
        for (int i = 0; i < 8; i++) {
            const int idx = tid + i * 128;
            const int row = idx >> 4;
            const int dq  = (idx & 15) << 2;
            float4 v = *(const float4*)&Kg[(k0 + row) * DH + dq];
            unsigned h0, l0, h1, l1;
            split2(v.x, v.y, h0, l0);
            split2(v.z, v.w, h1, l1);
            const int wo = row * ASTR + (dq >> 1);
            sKh[wo] = h0; sKh[wo + 1] = h1;
            sKl[wo] = l0; sKl[wo + 1] = l1;
        }
        // ---- stage V transposed [d][keypair] (pairs along key) ----
#pragma unroll
        for (int i = 0; i < 4; i++) {
            const int r = tid & 31;                       // key pair 0..31
            const int d = (((tid >> 5) + (i << 2)) << 2); // d chunk
            const float* p0 = &Vg[(k0 + 2 * r) * DH + d];
            float4 v0 = *(const float4*)p0;
            float4 v1 = *(const float4*)(p0 + DH);
            unsigned h, l;
            split2(v0.x, v1.x, h, l); sVh[(d + 0) * ASTR + r] = h; sVl[(d + 0) * ASTR + r] = l;
            split2(v0.y, v1.y, h, l); sVh[(d + 1) * ASTR + r] = h; sVl[(d + 1) * ASTR + r] = l;
            split2(v0.z, v1.z, h, l); sVh[(d + 2) * ASTR + r] = h; sVl[(d + 2) * ASTR + r] = l;
            split2(v0.w, v1.w, h, l); sVh[(d + 3) * ASTR + r] = h; sVl[(d + 3) * ASTR + r] = l;
        }
        __syncthreads();

        // ---- S = Q K^T : 8 n-frags x 4 k-steps x 3 MMAs ----
        float sacc[8][4];
#pragma unroll
        for (int nf = 0; nf < 8; nf++)
#pragma unroll
            for (int i = 0; i < 4; i++) sacc[nf][i] = 0.f;

#pragma unroll
        for (int ks = 0; ks < 4; ks++) {
            const int qb = (16 * w + g) * ASTR + ks * 8 + t;
            const unsigned qh0 = sQh[qb],     qh1 = sQh[qb + 8 * ASTR];
            const unsigned qh2 = sQh[qb + 4], qh3 = sQh[qb + 8 * ASTR + 4];
            const unsigned ql0 = sQl[qb],     ql1 = sQl[qb + 8 * ASTR];
            const unsigned ql2 = sQl[qb + 4], ql3 = sQl[qb + 8 * ASTR + 4];
#pragma unroll
            for (int nf = 0; nf < 8; nf++) {
                const int kb = (8 * nf + g) * ASTR + ks * 8 + t;
                const unsigned kh0 = sKh[kb], kh1 = sKh[kb + 4];
                const unsigned kl0 = sKl[kb], kl1 = sKl[kb + 4];
                mma16816(sacc[nf], qh0, qh1, qh2, qh3, kh0, kh1);
                mma16816(sacc[nf], qh0, qh1, qh2, qh3, kl0, kl1);
                mma16816(sacc[nf], ql0, ql1, ql2, ql3, kh0, kh1);
            }
        }

        // ---- causal mask on the diagonal tile ----
        if (kt == qt) {
            const int r0 = 16 * w + g, r1 = r0 + 8;
#pragma unroll
            for (int nf = 0; nf < 8; nf++) {
                const int c = 8 * nf + 2 * t;
                if (c     > r0) sacc[nf][0] = -INFINITY;
                if (c + 1 > r0) sacc[nf][1] = -INFINITY;
                if (c     > r1) sacc[nf][2] = -INFINITY;
                if (c + 1 > r1) sacc[nf][3] = -INFINITY;
            }
        }

        // ---- online softmax (rows g, g+8; lanes sharing a row = t group) ----
        float rm0 = -INFINITY, rm1 = -INFINITY;
#pragma unroll
        for (int nf = 0; nf < 8; nf++) {
            rm0 = fmaxf(rm0, fmaxf(sacc[nf][0], sacc[nf][1]));
            rm1 = fmaxf(rm1, fmaxf(sacc[nf][2], sacc[nf][3]));
        }
        rm0 = fmaxf(rm0, __shfl_xor_sync(0xffffffffu, rm0, 1));
        rm0 = fmaxf(rm0, __shfl_xor_sync(0xffffffffu, rm0, 2));
        rm1 = fmaxf(rm1, __shfl_xor_sync(0xffffffffu, rm1, 1));
        rm1 = fmaxf(rm1, __shfl_xor_sync(0xffffffffu, rm1, 2));

        const float mn0 = fmaxf(mrun0, rm0);
        const float mn1 = fmaxf(mrun1, rm1);
        const float c0  = __expf(mrun0 - mn0);
        const float c1  = __expf(mrun1 - mn1);

        float rs0 = 0.f, rs1 = 0.f;
#pragma unroll
        for (int nf = 0; nf < 8; nf++) {
            sacc[nf][0] = __expf(sacc[nf][0] - mn0); rs0 += sacc[nf][0];
            sacc[nf][1] = __expf(sacc[nf][1] - mn0); rs0 += sacc[nf][1];
            sacc[nf][2] = __expf(sacc[nf][2] - mn1); rs1 += sacc[nf][2];
            sacc[nf][3] = __expf(sacc[nf][3] - mn1); rs1 += sacc[nf][3];
        }
        rs0 += __shfl_xor_sync(0xffffffffu, rs0, 1);
        rs0 += __shfl_xor_sync(0xffffffffu, rs0, 2);
        rs1 += __shfl_xor_sync(0xffffffffu, rs1, 1);
        rs1 += __shfl_xor_sync(0xffffffffu, rs1, 2);

        lrun0 = lrun0 * c0 + rs0;
        lrun1 = lrun1 * c1 + rs1;
        mrun0 = mn0;
        mrun1 = mn1;
#pragma unroll
        for (int nf = 0; nf < 8; nf++) {
            oacc[nf][0] *= c0; oacc[nf][1] *= c0;
            oacc[nf][2] *= c1; oacc[nf][3] *= c1;
        }

        // ---- O += P V : S's C-fragments ARE P's A-fragments ----
#pragma unroll
        for (int ks = 0; ks < 4; ks++) {
            unsigned ph0, pl0, ph1, pl1, ph2, pl2, ph3, pl3;
            split2(sacc[2 * ks][0],     sacc[2 * ks][1],     ph0, pl0);
            split2(sacc[2 * ks][2],     sacc[2 * ks][3],     ph1, pl1);
            split2(sacc[2 * ks + 1][0], sacc[2 * ks + 1][1], ph2, pl2);
            split2(sacc[2 * ks + 1][2], sacc[2 * ks + 1][3], ph3, pl3);
#pragma unroll
            for (int nf = 0; nf < 8; nf++) {
                const int vb = (8 * nf + g) * ASTR + ks * 8 + t;
                const unsigned vh0 = sVh[vb], vh1 = sVh[vb + 4];
                const unsigned vl0 = sVl[vb], vl1 = sVl[vb + 4];
                mma16816(oacc[nf], ph0, ph1, ph2, ph3, vh0, vh1);
                mma16816(oacc[nf], ph0, ph1, ph2, ph3, vl0, vl1);
                mma16816(oacc[nf], pl0, pl1, pl2, pl3, vh0, vh1);
            }
        }
    }

    // ---- normalize and write to g_attn in [B,T,C] (C = h*64 + d) ----
    const float inv0 = 1.f / lrun0;
    const float inv1 = 1.f / lrun1;
    const int b  = bh >> 4;
    const int h  = bh & 15;
    const int r0 = q0 + 16 * w + g;
    const int r1 = r0 + 8;
#pragma unroll
    for (int nf = 0; nf < 8; nf++) {
        const int c = h * DH + 8 * nf + 2 * t;
        *(float2*)&g_attn[(size_t)(b * T_SEQ + r0) * DM + c] =
            make_float2(oacc[nf][0] * inv0, oacc[nf][1] * inv0);
        *(float2*)&g_attn[(size_t)(b * T_SEQ + r1) * DM + c] =
            make_float2(oacc[nf][2] * inv1, oacc[nf][3] * inv1);
    }
}

// ---------------------------------------------------------------------------
extern "C" void kernel_launch(void* const* d_in, const int* in_sizes, int n_in,
                              void* d_out, int out_size)
{
    const float* x      = (const float*)d_in[0];
    const float* W_qkv  = (const float*)d_in[1];
    const float* b_qkv  = (const float*)d_in[2];
    const float* W_proj = (const float*)d_in[3];
    const float* b_proj = (const float*)d_in[4];
    float* out = (float*)d_out;

    (void)in_sizes; (void)n_in; (void)out_size;

    float *WqT, *WpT;
    cudaGetSymbolAddress((void**)&WqT, g_WqT);
    cudaGetSymbolAddress((void**)&WpT, g_WpT);

    const int attn_smem = 6 * 64 * ASTR * 4;   // 55296 B
    cudaFuncSetAttribute(attn_mma_kernel,
                         cudaFuncAttributeMaxDynamicSharedMemorySize, attn_smem);

    // prep: transpose both weight matrices (one-time, ~10us)
    dim3 gw1(DM / 64, N_QKV / 64);
    wtrans_kernel<<<gw1, 256>>>(W_qkv, WqT, N_QKV);
    dim3 gw2(DM / 64, DM / 64);
    wtrans_kernel<<<gw2, 256>>>(W_proj, WpT, DM);

    dim3 gA(N_QKV / 128, MROWS / 128);   // (24, 32)
    mma_gemm_kernel<true><<<gA, 256>>>(x, WqT, b_qkv, nullptr);

    dim3 gB(T_SEQ / 64, BATCH * NH);     // (32, 32)
    attn_mma_kernel<<<gB, 128, attn_smem>>>();

    dim3 gC(DM / 128, MROWS / 128);      // (8, 32)
    mma_gemm_kernel<false><<<gC, 256>>>(nullptr, WpT, b_proj, out);
}

// round 13
// speedup vs baseline: 1.0712x; 1.0712x over previous
#include <cuda_runtime.h>
#include <cuda_bf16.h>
#include <math.h>

#define T_SEQ   2048
#define BATCH   2
#define DM      1024
#define NH      16
#define DH      64
#define MROWS   (BATCH*T_SEQ)    /* 4096 */
#define N_QKV   (3*DM)           /* 3072 */

// Scratch (allocation-free rule: __device__ globals). 64 MB total.
__device__ float g_Q[MROWS*DM];
__device__ float g_K[MROWS*DM];
__device__ float g_V[MROWS*DM];
__device__ float g_attn[MROWS*DM];

// ---------------------------------------------------------------------------
// bf16 split helpers: x = hi + lo with |x - hi - lo| ~ 2^-18 |x|.
// pack two (even, odd) bf16 into one 32-bit fragment word (low = even).
// ---------------------------------------------------------------------------
__device__ __forceinline__ void split2(float a, float b, unsigned &hi, unsigned &lo)
{
    __nv_bfloat16 ha = __float2bfloat16_rn(a);
    __nv_bfloat16 hb = __float2bfloat16_rn(b);
    __nv_bfloat162 h; h.x = ha; h.y = hb;
    hi = *reinterpret_cast<unsigned*>(&h);
    __nv_bfloat162 l = __floats2bfloat162_rn(a - __bfloat162float(ha),
                                             b - __bfloat162float(hb));
    lo = *reinterpret_cast<unsigned*>(&l);
}

__device__ __forceinline__ void mma16816(float* d,
    unsigned a0, unsigned a1, unsigned a2, unsigned a3,
    unsigned b0, unsigned b1)
{
    asm volatile(
        "mma.sync.aligned.m16n8k16.row.col.f32.bf16.bf16.f32 "
        "{%0,%1,%2,%3}, {%4,%5,%6,%7}, {%8,%9}, {%0,%1,%2,%3};\n"
        : "+f"(d[0]), "+f"(d[1]), "+f"(d[2]), "+f"(d[3])
        : "r"(a0), "r"(a1), "r"(a2), "r"(a3), "r"(b0), "r"(b1));
}

// ---------------------------------------------------------------------------
// Tensor-core GEMM (R6 VERBATIM — proven local optimum, 241us QKV):
// A[4096,1024] @ W[1024,NCOLS] + bias. Block 128x128x32, 8 warps (2x4),
// warp tile 64x32 = 4x4 m16n8k16 fragments. bf16 hi/lo split, 3 MMAs/frag.
// All LDGs issue before the first barrier (warp-skew absorbs latency);
// split2 ALU chains execute post-barrier with data in registers.
// ---------------------------------------------------------------------------
template<int NCOLS, bool SCATTER>
__global__ __launch_bounds__(256, 2)
void mma_gemm_kernel(const float* __restrict__ Ain, const float* __restrict__ W,
                     const float* __restrict__ bias, float* __restrict__ out)
{
    __shared__ unsigned Ahi[128*20], Alo[128*20], Bhi[128*20], Blo[128*20];

    const float* __restrict__ A = SCATTER ? Ain : (const float*)g_attn;

    const int tid  = threadIdx.x;
    const int lane = tid & 31;
    const int warp = tid >> 5;
    const int wm   = warp >> 2;     // 0..1
    const int wn   = warp & 3;      // 0..3
    const int g    = lane >> 2;     // 0..7
    const int t    = lane & 3;      // 0..3
    const int m0   = blockIdx.y * 128;
    const int n0   = blockIdx.x * 128;

    float acc[4][4][4];
#pragma unroll
    for (int mt = 0; mt < 4; mt++)
#pragma unroll
        for (int nt = 0; nt < 4; nt++)
#pragma unroll
            for (int i = 0; i < 4; i++) acc[mt][nt][i] = 0.f;

    const int ar  = tid >> 3;          // A row 0..31 (step 32)
    const int ak  = (tid & 7) << 2;    // A k offset
    const int bn  = tid & 127;         // B column (n)
    const int bk0 = (tid >> 7) << 2;   // 0 or 4

    for (int k0 = 0; k0 < DM; k0 += 8 * 4) {
        // ---- stage A (row-major [m][k]) ----
        float4 av[4];
#pragma unroll
        for (int i = 0; i < 4; i++)
            av[i] = *(const float4*)&A[(size_t)(m0 + ar + i * 32) * DM + k0 + ak];
        // ---- stage B transposed ([n][k]); global reads coalesced along n ----
        float bx[4][4];
#pragma unroll
        for (int gi = 0; gi < 4; gi++) {
            const int k = bk0 + gi * 8;
            const float* p = &W[(size_t)(k0 + k) * NCOLS + n0 + bn];
            bx[gi][0] = p[0];
            bx[gi][1] = p[NCOLS];
            bx[gi][2] = p[2 * NCOLS];
            bx[gi][3] = p[3 * NCOLS];
        }
        __syncthreads();               // previous tile fully consumed
#pragma unroll
        for (int i = 0; i < 4; i++) {
            const int r = ar + i * 32;
            unsigned h0, l0, h1, l1;
            split2(av[i].x, av[i].y, h0, l0);
            split2(av[i].z, av[i].w, h1, l1);
            const int w = r * 20 + (ak >> 1);
            Ahi[w] = h0; Ahi[w + 1] = h1;
            Alo[w] = l0; Alo[w + 1] = l1;
        }
#pragma unroll
        for (int gi = 0; gi < 4; gi++) {
            const int k = bk0 + gi * 8;
            unsigned h0, l0, h1, l1;
            split2(bx[gi][0], bx[gi][1], h0, l0);
            split2(bx[gi][2], bx[gi][3], h1, l1);
            const int w = bn * 20 + (k >> 1);
            Bhi[w] = h0; Bhi[w + 1] = h1;
            Blo[w] = l0; Blo[w + 1] = l1;
        }
        __syncthreads();

        // ---- compute: 2 k16-steps, 4x4 fragments, 3 MMAs each ----
#pragma unroll
        for (int ks = 0; ks < 2; ks++) {
            unsigned ah[4][4], al[4][4], bh[4][2], bl[4][2];
#pragma unroll
            for (int mt = 0; mt < 4; mt++) {
                const int base = (wm * 64 + mt * 16 + g) * 20 + ks * 8 + t;
                ah[mt][0] = Ahi[base];       ah[mt][1] = Ahi[base + 160];
                ah[mt][2] = Ahi[base + 4];   ah[mt][3] = Ahi[base + 164];
                al[mt][0] = Alo[base];       al[mt][1] = Alo[base + 160];
                al[mt][2] = Alo[base + 4];   al[mt][3] = Alo[base + 164];
            }
#pragma unroll
            for (int nt = 0; nt < 4; nt++) {
                const int base = (wn * 32 + nt * 8 + g) * 20 + ks * 8 + t;
                bh[nt][0] = Bhi[base];       bh[nt][1] = Bhi[base + 4];
                bl[nt][0] = Blo[base];       bl[nt][1] = Blo[base + 4];
            }
#pragma unroll
            for (int mt = 0; mt < 4; mt++)
#pragma unroll
                for (int nt = 0; nt < 4; nt++) {
                    mma16816(acc[mt][nt], ah[mt][0], ah[mt][1], ah[mt][2], ah[mt][3],
                             bh[nt][0], bh[nt][1]);
                    mma16816(acc[mt][nt], ah[mt][0], ah[mt][1], ah[mt][2], ah[mt][3],
                             bl[nt][0], bl[nt][1]);
                    mma16816(acc[mt][nt], al[mt][0], al[mt][1], al[mt][2], al[mt][3],
                             bh[nt][0], bh[nt][1]);
                }
        }
    }

    // ---- epilogue ----
#pragma unroll
    for (int mt = 0; mt < 4; mt++) {
        const int mrow0 = m0 + wm * 64 + mt * 16 + g;
#pragma unroll
        for (int nt = 0; nt < 4; nt++) {
            const int c = n0 + wn * 32 + nt * 8 + 2 * t;
            const float b0 = bias[c], b1 = bias[c + 1];
            const float v00 = acc[mt][nt][0] + b0;
            const float v01 = acc[mt][nt][1] + b1;
            const float v10 = acc[mt][nt][2] + b0;
            const float v11 = acc[mt][nt][3] + b1;
            if (SCATTER) {
                const int which = c >> 10;
                const int cc = c & (DM - 1);
                const int h  = cc >> 6;
                const int d  = cc & (DH - 1);
                float* dst = (which == 0) ? g_Q : (which == 1) ? g_K : g_V;
#pragma unroll
                for (int rr = 0; rr < 2; rr++) {
                    const int m   = mrow0 + rr * 8;
                    const int bb  = m >> 11;
                    const int tok = m & (T_SEQ - 1);
                    const size_t idx = ((size_t)(bb * NH + h) * T_SEQ + tok) * DH + d;
                    *(float2*)&dst[idx] = rr ? make_float2(v10, v11)
                                             : make_float2(v00, v01);
                }
            } else {
                *(float2*)&out[(size_t)mrow0 * DM + c]       = make_float2(v00, v01);
                *(float2*)&out[(size_t)(mrow0 + 8) * DM + c] = make_float2(v10, v11);
            }
        }
    }
}

// ---------------------------------------------------------------------------
// Attention (R6 + ONE change: __launch_bounds__(128, 4) caps regs at 128
// -> 4 CTAs/SM instead of 3; more cross-warp overlap for the serialized
// S-MMA -> softmax -> PV-MMA chain).
// CTA = 64 query rows x one (b,h); 4 warps, warp owns 16 rows.
// ---------------------------------------------------------------------------
#define ASTR 36
__global__ __launch_bounds__(128, 4)
void attn_mma_kernel()
{
    extern __shared__ unsigned smu[];
    unsigned* sQh = smu;
    unsigned* sQl = smu + 64 * ASTR;
    unsigned* sKh = smu + 2 * 64 * ASTR;
    unsigned* sKl = smu + 3 * 64 * ASTR;
    unsigned* sVh = smu + 4 * 64 * ASTR;   // transposed: [d][keypair]
    unsigned* sVl = smu + 5 * 64 * ASTR;

    const int tid  = threadIdx.x;
    const int lane = tid & 31;
    const int w    = tid >> 5;      // warp 0..3, rows 16w..16w+15
    const int g    = lane >> 2;     // 0..7
    const int t    = lane & 3;      // 0..3
    const int qt   = (int)(gridDim.x - 1) - (int)blockIdx.x;  // longest first
    const int bh   = blockIdx.y;
    const int q0   = qt * 64;

    const float* Qg = g_Q + (size_t)bh * T_SEQ * DH;
    const float* Kg = g_K + (size_t)bh * T_SEQ * DH;
    const float* Vg = g_V + (size_t)bh * T_SEQ * DH;

    // ---- stage Q once, pre-scaled by 1/sqrt(Dh) ----
#pragma unroll
    for (int i = 0; i < 8; i++) {
        const int idx = tid + i * 128;
        const int row = idx >> 4;
        const int dq  = (idx & 15) << 2;
        float4 v = *(const float4*)&Qg[(q0 + row) * DH + dq];
        unsigned h0, l0, h1, l1;
        split2(v.x * 0.125f, v.y * 0.125f, h0, l0);
        split2(v.z * 0.125f, v.w * 0.125f, h1, l1);
        const int wo = row * ASTR + (dq >> 1);
        sQh[wo] = h0; sQh[wo + 1] = h1;
        sQl[wo] = l0; sQl[wo + 1] = l1;
    }

    float oacc[8][4];
#pragma unroll
    for (int nf = 0; nf < 8; nf++)
#pragma unroll
        for (int i = 0; i < 4; i++) oacc[nf][i] = 0.f;
    float mrun0 = -INFINITY, mrun1 = -INFINITY;
    float lrun0 = 0.f, lrun1 = 0.f;

    for (int kt = 0; kt <= qt; kt++) {
        __syncthreads();   // Q visible (iter 0) / prior frag reads done
        const int k0 = kt * 64;

        // ---- stage K natural [key][d] ----
#pragma unroll
        for (int i = 0; i < 8; i++) {
            const int idx = tid + i * 128;
            const int row = idx >> 4;
            const int dq  = (idx & 15) << 2;
            float4 v = *(const float4*)&Kg[(k0 + row) * DH + dq];
            unsigned h0, l0, h1, l1;
            split2(v.x, v.y, h0, l0);
            split2(v.z, v.w, h1, l1);
            const int wo = row * ASTR + (dq >> 1);
            sKh[wo] = h0; sKh[wo + 1] = h1;
            sKl[wo] = l0; sKl[wo + 1] = l1;
        }
        // ---- stage V transposed [d][keypair] (pairs along key) ----
#pragma unroll
        for (int i = 0; i < 4; i++) {
            const int r = tid & 31;                       // key pair 0..31
            const int d = (((tid >> 5) + (i << 2)) << 2); // d chunk
            const float* p0 = &Vg[(k0 + 2 * r) * DH + d];
            float4 v0 = *(const float4*)p0;
            float4 v1 = *(const float4*)(p0 + DH);
            unsigned h, l;
            split2(v0.x, v1.x, h, l); sVh[(d + 0) * ASTR + r] = h; sVl[(d + 0) * ASTR + r] = l;
            split2(v0.y, v1.y, h, l); sVh[(d + 1) * ASTR + r] = h; sVl[(d + 1) * ASTR + r] = l;
            split2(v0.z, v1.z, h, l); sVh[(d + 2) * ASTR + r] = h; sVl[(d + 2) * ASTR + r] = l;
            split2(v0.w, v1.w, h, l); sVh[(d + 3) * ASTR + r] = h; sVl[(d + 3) * ASTR + r] = l;
        }
        __syncthreads();

        // ---- S = Q K^T : 8 n-frags x 4 k-steps x 3 MMAs ----
        float sacc[8][4];
#pragma unroll
        for (int nf = 0; nf < 8; nf++)
#pragma unroll
            for (int i = 0; i < 4; i++) sacc[nf][i] = 0.f;

#pragma unroll
        for (int ks = 0; ks < 4; ks++) {
            const int qb = (16 * w + g) * ASTR + ks * 8 + t;
            const unsigned qh0 = sQh[qb],     qh1 = sQh[qb + 8 * ASTR];
            const unsigned qh2 = sQh[qb + 4], qh3 = sQh[qb + 8 * ASTR + 4];
            const unsigned ql0 = sQl[qb],     ql1 = sQl[qb + 8 * ASTR];
            const unsigned ql2 = sQl[qb + 4], ql3 = sQl[qb + 8 * ASTR + 4];
#pragma unroll
            for (int nf = 0; nf < 8; nf++) {
                const int kb = (8 * nf + g) * ASTR + ks * 8 + t;
                const unsigned kh0 = sKh[kb], kh1 = sKh[kb + 4];
                const unsigned kl0 = sKl[kb], kl1 = sKl[kb + 4];
                mma16816(sacc[nf], qh0, qh1, qh2, qh3, kh0, kh1);
                mma16816(sacc[nf], qh0, qh1, qh2, qh3, kl0, kl1);
                mma16816(sacc[nf], ql0, ql1, ql2, ql3, kh0, kh1);
            }
        }

        // ---- causal mask on the diagonal tile ----
        if (kt == qt) {
            const int r0 = 16 * w + g, r1 = r0 + 8;
#pragma unroll
            for (int nf = 0; nf < 8; nf++) {
                const int c = 8 * nf + 2 * t;
                if (c     > r0) sacc[nf][0] = -INFINITY;
                if (c + 1 > r0) sacc[nf][1] = -INFINITY;
                if (c     > r1) sacc[nf][2] = -INFINITY;
                if (c + 1 > r1) sacc[nf][3] = -INFINITY;
            }
        }

        // ---- online softmax (rows g, g+8; lanes sharing a row = t group) ----
        float rm0 = -INFINITY, rm1 = -INFINITY;
#pragma unroll
        for (int nf = 0; nf < 8; nf++) {
            rm0 = fmaxf(rm0, fmaxf(sacc[nf][0], sacc[nf][1]));
            rm1 = fmaxf(rm1, fmaxf(sacc[nf][2], sacc[nf][3]));
        }
        rm0 = fmaxf(rm0, __shfl_xor_sync(0xffffffffu, rm0, 1));
        rm0 = fmaxf(rm0, __shfl_xor_sync(0xffffffffu, rm0, 2));
        rm1 = fmaxf(rm1, __shfl_xor_sync(0xffffffffu, rm1, 1));
        rm1 = fmaxf(rm1, __shfl_xor_sync(0xffffffffu, rm1, 2));

        const float mn0 = fmaxf(mrun0, rm0);
        const float mn1 = fmaxf(mrun1, rm1);
        const float c0  = __expf(mrun0 - mn0);
        const float c1  = __expf(mrun1 - mn1);

        float rs0 = 0.f, rs1 = 0.f;
#pragma unroll
        for (int nf = 0; nf < 8; nf++) {
            sacc[nf][0] = __expf(sacc[nf][0] - mn0); rs0 += sacc[nf][0];
            sacc[nf][1] = __expf(sacc[nf][1] - mn0); rs0 += sacc[nf][1];
            sacc[nf][2] = __expf(sacc[nf][2] - mn1); rs1 += sacc[nf][2];
            sacc[nf][3] = __expf(sacc[nf][3] - mn1); rs1 += sacc[nf][3];
        }
        rs0 += __shfl_xor_sync(0xffffffffu, rs0, 1);
        rs0 += __shfl_xor_sync(0xffffffffu, rs0, 2);
        rs1 += __shfl_xor_sync(0xffffffffu, rs1, 1);
        rs1 += __shfl_xor_sync(0xffffffffu, rs1, 2);

        lrun0 = lrun0 * c0 + rs0;
        lrun1 = lrun1 * c1 + rs1;
        mrun0 = mn0;
        mrun1 = mn1;
#pragma unroll
        for (int nf = 0; nf < 8; nf++) {
            oacc[nf][0] *= c0; oacc[nf][1] *= c0;
            oacc[nf][2] *= c1; oacc[nf][3] *= c1;
        }

        // ---- O += P V : S's C-fragments ARE P's A-fragments ----
#pragma unroll
        for (int ks = 0; ks < 4; ks++) {
            unsigned ph0, pl0, ph1, pl1, ph2, pl2, ph3, pl3;
            split2(sacc[2 * ks][0],     sacc[2 * ks][1],     ph0, pl0);
            split2(sacc[2 * ks][2],     sacc[2 * ks][3],     ph1, pl1);
            split2(sacc[2 * ks + 1][0], sacc[2 * ks + 1][1], ph2, pl2);
            split2(sacc[2 * ks + 1][2], sacc[2 * ks + 1][3], ph3, pl3);
#pragma unroll
            for (int nf = 0; nf < 8; nf++) {
                const int vb = (8 * nf + g) * ASTR + ks * 8 + t;
                const unsigned vh0 = sVh[vb], vh1 = sVh[vb + 4];
                const unsigned vl0 = sVl[vb], vl1 = sVl[vb + 4];
                mma16816(oacc[nf], ph0, ph1, ph2, ph3, vh0, vh1);
                mma16816(oacc[nf], ph0, ph1, ph2, ph3, vl0, vl1);
                mma16816(oacc[nf], pl0, pl1, pl2, pl3, vh0, vh1);
            }
        }
    }

    // ---- normalize and write to g_attn in [B,T,C] (C = h*64 + d) ----
    const float inv0 = 1.f / lrun0;
    const float inv1 = 1.f / lrun1;
    const int b  = bh >> 4;
    const int h  = bh & 15;
    const int r0 = q0 + 16 * w + g;
    const int r1 = r0 + 8;
#pragma unroll
    for (int nf = 0; nf < 8; nf++) {
        const int c = h * DH + 8 * nf + 2 * t;
        *(float2*)&g_attn[(size_t)(b * T_SEQ + r0) * DM + c] =
            make_float2(oacc[nf][0] * inv0, oacc[nf][1] * inv0);
        *(float2*)&g_attn[(size_t)(b * T_SEQ + r1) * DM + c] =
            make_float2(oacc[nf][2] * inv1, oacc[nf][3] * inv1);
    }
}

// ---------------------------------------------------------------------------
extern "C" void kernel_launch(void* const* d_in, const int* in_sizes, int n_in,
                              void* d_out, int out_size)
{
    const float* x      = (const float*)d_in[0];
    const float* W_qkv  = (const float*)d_in[1];
    const float* b_qkv  = (const float*)d_in[2];
    const float* W_proj = (const float*)d_in[3];
    const float* b_proj = (const float*)d_in[4];
    float* out = (float*)d_out;

    (void)in_sizes; (void)n_in; (void)out_size;

    const int attn_smem = 6 * 64 * ASTR * 4;   // 55296 B
    cudaFuncSetAttribute(attn_mma_kernel,
                         cudaFuncAttributeMaxDynamicSharedMemorySize, attn_smem);

    dim3 gA(N_QKV / 128, MROWS / 128);   // (24, 32)
    mma_gemm_kernel<N_QKV, true><<<gA, 256>>>(x, W_qkv, b_qkv, nullptr);

    dim3 gB(T_SEQ / 64, BATCH * NH);     // (32, 32)
    attn_mma_kernel<<<gB, 128, attn_smem>>>();

    dim3 gC(DM / 128, MROWS / 128);      // (8, 32)
    mma_gemm_kernel<DM, false><<<gC, 256>>>(nullptr, W_proj, b_proj, out);
}

// round 15
// speedup vs baseline: 1.0715x; 1.0003x over previous
#include <cuda_runtime.h>
#include <cuda_bf16.h>
#include <math.h>

#define T_SEQ   2048
#define BATCH   2
#define DM      1024
#define NH      16
#define DH      64
#define MROWS   (BATCH*T_SEQ)    /* 4096 */
#define N_QKV   (3*DM)           /* 3072 */

// Scratch (allocation-free rule: __device__ globals). 64 MB total.
__device__ float g_Q[MROWS*DM];
__device__ float g_K[MROWS*DM];
__device__ float g_V[MROWS*DM];
__device__ float g_attn[MROWS*DM];

// ---------------------------------------------------------------------------
// bf16 split helpers: x = hi + lo with |x - hi - lo| ~ 2^-18 |x|.
// pack two (even, odd) bf16 into one 32-bit fragment word (low = even).
// ---------------------------------------------------------------------------
__device__ __forceinline__ void split2(float a, float b, unsigned &hi, unsigned &lo)
{
    __nv_bfloat16 ha = __float2bfloat16_rn(a);
    __nv_bfloat16 hb = __float2bfloat16_rn(b);
    __nv_bfloat162 h; h.x = ha; h.y = hb;
    hi = *reinterpret_cast<unsigned*>(&h);
    __nv_bfloat162 l = __floats2bfloat162_rn(a - __bfloat162float(ha),
                                             b - __bfloat162float(hb));
    lo = *reinterpret_cast<unsigned*>(&l);
}

__device__ __forceinline__ void mma16816(float* d,
    unsigned a0, unsigned a1, unsigned a2, unsigned a3,
    unsigned b0, unsigned b1)
{
    asm volatile(
        "mma.sync.aligned.m16n8k16.row.col.f32.bf16.bf16.f32 "
        "{%0,%1,%2,%3}, {%4,%5,%6,%7}, {%8,%9}, {%0,%1,%2,%3};\n"
        : "+f"(d[0]), "+f"(d[1]), "+f"(d[2]), "+f"(d[3])
        : "r"(a0), "r"(a1), "r"(a2), "r"(a3), "r"(b0), "r"(b1));
}

// ---------------------------------------------------------------------------
// Tensor-core GEMM (R6 VERBATIM — proven local optimum, ~236us QKV):
// A[4096,1024] @ W[1024,NCOLS] + bias. Block 128x128x32, 8 warps (2x4),
// warp tile 64x32 = 4x4 m16n8k16 fragments. bf16 hi/lo split, 3 MMAs/frag.
// All LDGs issue before the first barrier (warp-skew absorbs latency);
// split2 ALU chains execute post-barrier with data in registers. FROZEN.
// ---------------------------------------------------------------------------
template<int NCOLS, bool SCATTER>
__global__ __launch_bounds__(256, 2)
void mma_gemm_kernel(const float* __restrict__ Ain, const float* __restrict__ W,
                     const float* __restrict__ bias, float* __restrict__ out)
{
    __shared__ unsigned Ahi[128*20], Alo[128*20], Bhi[128*20], Blo[128*20];

    const float* __restrict__ A = SCATTER ? Ain : (const float*)g_attn;

    const int tid  = threadIdx.x;
    const int lane = tid & 31;
    const int warp = tid >> 5;
    const int wm   = warp >> 2;     // 0..1
    const int wn   = warp & 3;      // 0..3
    const int g    = lane >> 2;     // 0..7
    const int t    = lane & 3;      // 0..3
    const int m0   = blockIdx.y * 128;
    const int n0   = blockIdx.x * 128;

    float acc[4][4][4];
#pragma unroll
    for (int mt = 0; mt < 4; mt++)
#pragma unroll
        for (int nt = 0; nt < 4; nt++)
#pragma unroll
            for (int i = 0; i < 4; i++) acc[mt][nt][i] = 0.f;

    const int ar  = tid >> 3;          // A row 0..31 (step 32)
    const int ak  = (tid & 7) << 2;    // A k offset
    const int bn  = tid & 127;         // B column (n)
    const int bk0 = (tid >> 7) << 2;   // 0 or 4

    for (int k0 = 0; k0 < DM; k0 += 32) {
        // ---- all LDGs before the barrier ----
        float4 av[4];
#pragma unroll
        for (int i = 0; i < 4; i++)
            av[i] = *(const float4*)&A[(size_t)(m0 + ar + i * 32) * DM + k0 + ak];
        float bx[4][4];
#pragma unroll
        for (int gi = 0; gi < 4; gi++) {
            const int k = bk0 + gi * 8;
            const float* p = &W[(size_t)(k0 + k) * NCOLS + n0 + bn];
            bx[gi][0] = p[0];
            bx[gi][1] = p[NCOLS];
            bx[gi][2] = p[2 * NCOLS];
            bx[gi][3] = p[3 * NCOLS];
        }
        __syncthreads();               // previous tile fully consumed
#pragma unroll
        for (int i = 0; i < 4; i++) {
            const int r = ar + i * 32;
            unsigned h0, l0, h1, l1;
            split2(av[i].x, av[i].y, h0, l0);
            split2(av[i].z, av[i].w, h1, l1);
            const int w = r * 20 + (ak >> 1);
            Ahi[w] = h0; Ahi[w + 1] = h1;
            Alo[w] = l0; Alo[w + 1] = l1;
        }
#pragma unroll
        for (int gi = 0; gi < 4; gi++) {
            const int k = bk0 + gi * 8;
            unsigned h0, l0, h1, l1;
            split2(bx[gi][0], bx[gi][1], h0, l0);
            split2(bx[gi][2], bx[gi][3], h1, l1);
            const int w = bn * 20 + (k >> 1);
            Bhi[w] = h0; Bhi[w + 1] = h1;
            Blo[w] = l0; Blo[w + 1] = l1;
        }
        __syncthreads();

        // ---- compute: 2 k16-steps, 4x4 fragments, 3 MMAs each ----
#pragma unroll
        for (int ks = 0; ks < 2; ks++) {
            unsigned ah[4][4], al[4][4], bh[4][2], bl[4][2];
#pragma unroll
            for (int mt = 0; mt < 4; mt++) {
                const int base = (wm * 64 + mt * 16 + g) * 20 + ks * 8 + t;
                ah[mt][0] = Ahi[base];       ah[mt][1] = Ahi[base + 160];
                ah[mt][2] = Ahi[base + 4];   ah[mt][3] = Ahi[base + 164];
                al[mt][0] = Alo[base];       al[mt][1] = Alo[base + 160];
                al[mt][2] = Alo[base + 4];   al[mt][3] = Alo[base + 164];
            }
#pragma unroll
            for (int nt = 0; nt < 4; nt++) {
                const int base = (wn * 32 + nt * 8 + g) * 20 + ks * 8 + t;
                bh[nt][0] = Bhi[base];       bh[nt][1] = Bhi[base + 4];
                bl[nt][0] = Blo[base];       bl[nt][1] = Blo[base + 4];
            }
#pragma unroll
            for (int mt = 0; mt < 4; mt++)
#pragma unroll
                for (int nt = 0; nt < 4; nt++) {
                    mma16816(acc[mt][nt], ah[mt][0], ah[mt][1], ah[mt][2], ah[mt][3],
                             bh[nt][0], bh[nt][1]);
                    mma16816(acc[mt][nt], ah[mt][0], ah[mt][1], ah[mt][2], ah[mt][3],
                             bl[nt][0], bl[nt][1]);
                    mma16816(acc[mt][nt], al[mt][0], al[mt][1], al[mt][2], al[mt][3],
                             bh[nt][0], bh[nt][1]);
                }
        }
    }

    // ---- epilogue ----
#pragma unroll
    for (int mt = 0; mt < 4; mt++) {
        const int mrow0 = m0 + wm * 64 + mt * 16 + g;
#pragma unroll
        for (int nt = 0; nt < 4; nt++) {
            const int c = n0 + wn * 32 + nt * 8 + 2 * t;
            const float b0 = bias[c], b1 = bias[c + 1];
            const float v00 = acc[mt][nt][0] + b0;
            const float v01 = acc[mt][nt][1] + b1;
            const float v10 = acc[mt][nt][2] + b0;
            const float v11 = acc[mt][nt][3] + b1;
            if (SCATTER) {
                const int which = c >> 10;
                const int cc = c & (DM - 1);
                const int h  = cc >> 6;
                const int d  = cc & (DH - 1);
                float* dst = (which == 0) ? g_Q : (which == 1) ? g_K : g_V;
#pragma unroll
                for (int rr = 0; rr < 2; rr++) {
                    const int m   = mrow0 + rr * 8;
                    const int bb  = m >> 11;
                    const int tok = m & (T_SEQ - 1);
                    const size_t idx = ((size_t)(bb * NH + h) * T_SEQ + tok) * DH + d;
                    *(float2*)&dst[idx] = rr ? make_float2(v10, v11)
                                             : make_float2(v00, v01);
                }
            } else {
                *(float2*)&out[(size_t)mrow0 * DM + c]       = make_float2(v00, v01);
                *(float2*)&out[(size_t)(mrow0 + 8) * DM + c] = make_float2(v10, v11);
            }
        }
    }
}

// ---------------------------------------------------------------------------
// Attention (R13 + ONE change: K/V LDGs hoisted ABOVE the first barrier —
// the proven R6-GEMM ordering. Barrier warp-skew absorbs global-load
// latency; split2+STS run post-barrier with data already in registers.)
// CTA = 64 query rows x one (b,h); 4 warps, warp owns 16 rows. 4 CTAs/SM.
// ---------------------------------------------------------------------------
#define ASTR 36
__global__ __launch_bounds__(128, 4)
void attn_mma_kernel()
{
    extern __shared__ unsigned smu[];
    unsigned* sQh = smu;
    unsigned* sQl = smu + 64 * ASTR;
    unsigned* sKh = smu + 2 * 64 * ASTR;
    unsigned* sKl = smu + 3 * 64 * ASTR;
    unsigned* sVh = smu + 4 * 64 * ASTR;   // transposed: [d][keypair]
    unsigned* sVl = smu + 5 * 64 * ASTR;

    const int tid  = threadIdx.x;
    const int lane = tid & 31;
    const int w    = tid >> 5;      // warp 0..3, rows 16w..16w+15
    const int g    = lane >> 2;     // 0..7
    const int t    = lane & 3;      // 0..3
    const int qt   = (int)(gridDim.x - 1) - (int)blockIdx.x;  // longest first
    const int bh   = blockIdx.y;
    const int q0   = qt * 64;

    const float* Qg = g_Q + (size_t)bh * T_SEQ * DH;
    const float* Kg = g_K + (size_t)bh * T_SEQ * DH;
    const float* Vg = g_V + (size_t)bh * T_SEQ * DH;

    // staging maps (constant across iterations)
    const int krow = tid >> 4;                 // K row half-index base
    const int kdq  = (tid & 15) << 2;          // K d offset
    const int vr   = tid & 31;                 // V key pair
    const int vd0  = (tid >> 5) << 2;          // V d base (stride 16 over i)

    // ---- stage Q once, pre-scaled by 1/sqrt(Dh) ----
#pragma unroll
    for (int i = 0; i < 8; i++) {
        const int row = krow + i * 8;
        float4 v = *(const float4*)&Qg[(q0 + row) * DH + kdq];
        unsigned h0, l0, h1, l1;
        split2(v.x * 0.125f, v.y * 0.125f, h0, l0);
        split2(v.z * 0.125f, v.w * 0.125f, h1, l1);
        const int wo = row * ASTR + (kdq >> 1);
        sQh[wo] = h0; sQh[wo + 1] = h1;
        sQl[wo] = l0; sQl[wo + 1] = l1;
    }

    float oacc[8][4];
#pragma unroll
    for (int nf = 0; nf < 8; nf++)
#pragma unroll
        for (int i = 0; i < 4; i++) oacc[nf][i] = 0.f;
    float mrun0 = -INFINITY, mrun1 = -INFINITY;
    float lrun0 = 0.f, lrun1 = 0.f;

    for (int kt = 0; kt <= qt; kt++) {
        const int k0 = kt * 64;

        // ---- issue ALL K/V loads BEFORE the barrier ----
        float4 kv[8];
#pragma unroll
        for (int i = 0; i < 8; i++)
            kv[i] = *(const float4*)&Kg[(k0 + krow + i * 8) * DH + kdq];
        float4 va[4], vb[4];
#pragma unroll
        for (int i = 0; i < 4; i++) {
            const float* p0 = &Vg[(size_t)(k0 + 2 * vr) * DH + vd0 + i * 16];
            va[i] = *(const float4*)p0;
            vb[i] = *(const float4*)(p0 + DH);
        }
        __syncthreads();   // prior compute done reading smem (skew hides LDGs)

        // ---- split + STS from registers ----
#pragma unroll
        for (int i = 0; i < 8; i++) {
            const int row = krow + i * 8;
            unsigned h0, l0, h1, l1;
            split2(kv[i].x, kv[i].y, h0, l0);
            split2(kv[i].z, kv[i].w, h1, l1);
            const int wo = row * ASTR + (kdq >> 1);
            sKh[wo] = h0; sKh[wo + 1] = h1;
            sKl[wo] = l0; sKl[wo + 1] = l1;
        }
#pragma unroll
        for (int i = 0; i < 4; i++) {
            const int d = vd0 + i * 16;
            unsigned h, l;
            split2(va[i].x, vb[i].x, h, l); sVh[(d + 0) * ASTR + vr] = h; sVl[(d + 0) * ASTR + vr] = l;
            split2(va[i].y, vb[i].y, h, l); sVh[(d + 1) * ASTR + vr] = h; sVl[(d + 1) * ASTR + vr] = l;
            split2(va[i].z, vb[i].z, h, l); sVh[(d + 2) * ASTR + vr] = h; sVl[(d + 2) * ASTR + vr] = l;
            split2(va[i].w, vb[i].w, h, l); sVh[(d + 3) * ASTR + vr] = h; sVl[(d + 3) * ASTR + vr] = l;
        }
        __syncthreads();

        // ---- S = Q K^T : 8 n-frags x 4 k-steps x 3 MMAs ----
        float sacc[8][4];
#pragma unroll
        for (int nf = 0; nf < 8; nf++)
#pragma unroll
            for (int i = 0; i < 4; i++) sacc[nf][i] = 0.f;

#pragma unroll
        for (int ks = 0; ks < 4; ks++) {
            const int qb = (16 * w + g) * ASTR + ks * 8 + t;
            const unsigned qh0 = sQh[qb],     qh1 = sQh[qb + 8 * ASTR];
            const unsigned qh2 = sQh[qb + 4], qh3 = sQh[qb + 8 * ASTR + 4];
            const unsigned ql0 = sQl[qb],     ql1 = sQl[qb + 8 * ASTR];
            const unsigned ql2 = sQl[qb + 4], ql3 = sQl[qb + 8 * ASTR + 4];
#pragma unroll
            for (int nf = 0; nf < 8; nf++) {
                const int kb = (8 * nf + g) * ASTR + ks * 8 + t;
                const unsigned kh0 = sKh[kb], kh1 = sKh[kb + 4];
                const unsigned kl0 = sKl[kb], kl1 = sKl[kb + 4];
                mma16816(sacc[nf], qh0, qh1, qh2, qh3, kh0, kh1);
                mma16816(sacc[nf], qh0, qh1, qh2, qh3, kl0, kl1);
                mma16816(sacc[nf], ql0, ql1, ql2, ql3, kh0, kh1);
            }
        }

        // ---- causal mask on the diagonal tile ----
        if (kt == qt) {
            const int r0 = 16 * w + g, r1 = r0 + 8;
#pragma unroll
            for (int nf = 0; nf < 8; nf++) {
                const int c = 8 * nf + 2 * t;
                if (c     > r0) sacc[nf][0] = -INFINITY;
                if (c + 1 > r0) sacc[nf][1] = -INFINITY;
                if (c     > r1) sacc[nf][2] = -INFINITY;
                if (c + 1 > r1) sacc[nf][3] = -INFINITY;
            }
        }

        // ---- online softmax (rows g, g+8; lanes sharing a row = t group) ----
        float rm0 = -INFINITY, rm1 = -INFINITY;
#pragma unroll
        for (int nf = 0; nf < 8; nf++) {
            rm0 = fmaxf(rm0, fmaxf(sacc[nf][0], sacc[nf][1]));
            rm1 = fmaxf(rm1, fmaxf(sacc[nf][2], sacc[nf][3]));
        }
        rm0 = fmaxf(rm0, __shfl_xor_sync(0xffffffffu, rm0, 1));
        rm0 = fmaxf(rm0, __shfl_xor_sync(0xffffffffu, rm0, 2));
        rm1 = fmaxf(rm1, __shfl_xor_sync(0xffffffffu, rm1, 1));
        rm1 = fmaxf(rm1, __shfl_xor_sync(0xffffffffu, rm1, 2));

        const float mn0 = fmaxf(mrun0, rm0);
        const float mn1 = fmaxf(mrun1, rm1);
        const float c0  = __expf(mrun0 - mn0);
        const float c1  = __expf(mrun1 - mn1);

        float rs0 = 0.f, rs1 = 0.f;
#pragma unroll
        for (int nf = 0; nf < 8; nf++) {
            sacc[nf][0] = __expf(sacc[nf][0] - mn0); rs0 += sacc[nf][0];
            sacc[nf][1] = __expf(sacc[nf][1] - mn0); rs0 += sacc[nf][1];
            sacc[nf][2] = __expf(sacc[nf][2] - mn1); rs1 += sacc[nf][2];
            sacc[nf][3] = __expf(sacc[nf][3] - mn1); rs1 += sacc[nf][3];
        }
        rs0 += __shfl_xor_sync(0xffffffffu, rs0, 1);
        rs0 += __shfl_xor_sync(0xffffffffu, rs0, 2);
        rs1 += __shfl_xor_sync(0xffffffffu, rs1, 1);
        rs1 += __shfl_xor_sync(0xffffffffu, rs1, 2);

        lrun0 = lrun0 * c0 + rs0;
        lrun1 = lrun1 * c1 + rs1;
        mrun0 = mn0;
        mrun1 = mn1;
#pragma unroll
        for (int nf = 0; nf < 8; nf++) {
            oacc[nf][0] *= c0; oacc[nf][1] *= c0;
            oacc[nf][2] *= c1; oacc[nf][3] *= c1;
        }

        // ---- O += P V : S's C-fragments ARE P's A-fragments ----
#pragma unroll
        for (int ks = 0; ks < 4; ks++) {
            unsigned ph0, pl0, ph1, pl1, ph2, pl2, ph3, pl3;
            split2(sacc[2 * ks][0],     sacc[2 * ks][1],     ph0, pl0);
            split2(sacc[2 * ks][2],     sacc[2 * ks][3],     ph1, pl1);
            split2(sacc[2 * ks + 1][0], sacc[2 * ks + 1][1], ph2, pl2);
            split2(sacc[2 * ks + 1][2], sacc[2 * ks + 1][3], ph3, pl3);
#pragma unroll
            for (int nf = 0; nf < 8; nf++) {
                const int vbi = (8 * nf + g) * ASTR + ks * 8 + t;
                const unsigned vh0 = sVh[vbi], vh1 = sVh[vbi + 4];
                const unsigned vl0 = sVl[vbi], vl1 = sVl[vbi + 4];
                mma16816(oacc[nf], ph0, ph1, ph2, ph3, vh0, vh1);
                mma16816(oacc[nf], ph0, ph1, ph2, ph3, vl0, vl1);
                mma16816(oacc[nf], pl0, pl1, pl2, pl3, vh0, vh1);
            }
        }
    }

    // ---- normalize and write to g_attn in [B,T,C] (C = h*64 + d) ----
    const float inv0 = 1.f / lrun0;
    const float inv1 = 1.f / lrun1;
    const int b  = bh >> 4;
    const int h  = bh & 15;
    const int r0 = q0 + 16 * w + g;
    const int r1 = r0 + 8;
#pragma unroll
    for (int nf = 0; nf < 8; nf++) {
        const int c = h * DH + 8 * nf + 2 * t;
        *(float2*)&g_attn[(size_t)(b * T_SEQ + r0) * DM + c] =
            make_float2(oacc[nf][0] * inv0, oacc[nf][1] * inv0);
        *(float2*)&g_attn[(size_t)(b * T_SEQ + r1) * DM + c] =
            make_float2(oacc[nf][2] * inv1, oacc[nf][3] * inv1);
    }
}

// ---------------------------------------------------------------------------
extern "C" void kernel_launch(void* const* d_in, const int* in_sizes, int n_in,
                              void* d_out, int out_size)
{
    const float* x      = (const float*)d_in[0];
    const float* W_qkv  = (const float*)d_in[1];
    const float* b_qkv  = (const float*)d_in[2];
    const float* W_proj = (const float*)d_in[3];
    const float* b_proj = (const float*)d_in[4];
    float* out = (float*)d_out;

    (void)in_sizes; (void)n_in; (void)out_size;

    const int attn_smem = 6 * 64 * ASTR * 4;   // 55296 B
    cudaFuncSetAttribute(attn_mma_kernel,
                         cudaFuncAttributeMaxDynamicSharedMemorySize, attn_smem);

    dim3 gA(N_QKV / 128, MROWS / 128);   // (24, 32)
    mma_gemm_kernel<N_QKV, true><<<gA, 256>>>(x, W_qkv, b_qkv, nullptr);

    dim3 gB(T_SEQ / 64, BATCH * NH);     // (32, 32)
    attn_mma_kernel<<<gB, 128, attn_smem>>>();

    dim3 gC(DM / 128, MROWS / 128);      // (8, 32)
    mma_gemm_kernel<DM, false><<<gC, 256>>>(nullptr, W_proj, b_proj, out);
}